// round 1
// baseline (speedup 1.0000x reference)
#include <cuda_runtime.h>
#include <math.h>

#define NN 100000
#define EE 1600000
#define NF 133
#define HD 128

// ---------------- device scratch (static, no runtime alloc) ----------------
__device__ float g_h[NN * HD];      // GEMM output (pre-aggregation)
__device__ float g_a[NN * HD];      // aggregated activations (layer input)
__device__ float g_dinv[NN];
__device__ int   g_cnt[NN];
__device__ int   g_rowptr[NN];
__device__ int   g_fill[NN];
__device__ int   g_col[EE];
__device__ float g_wgt[EE];
__device__ int   g_bsum[256];
__device__ int   g_is64;

// ---------------- edge dtype probe ----------------
// If edge_index is int64, every odd 32-bit word (high half) is 0 for values < 2^31.
// If int32, odd words are random node ids (P(all 256 zero) ~ 0).
__global__ void k_probe(const int* __restrict__ ei) {
    __shared__ int nz;
    if (threadIdx.x == 0) nz = 0;
    __syncthreads();
    int v = ei[threadIdx.x * 2 + 1];
    if (v != 0) atomicAdd(&nz, 1);
    __syncthreads();
    if (threadIdx.x == 0) g_is64 = (nz == 0) ? 1 : 0;
}

__device__ __forceinline__ int edge_val(const void* ei, long long idx) {
    if (g_is64) return (int)((const long long*)ei)[idx];
    return ((const int*)ei)[idx];
}

// ---------------- CSR build ----------------
__global__ void k_zero_cnt(int n) {
    int i = blockIdx.x * blockDim.x + threadIdx.x;
    if (i < n) g_cnt[i] = 0;
}

__global__ void k_count(const void* __restrict__ ei, int e) {
    int i = blockIdx.x * blockDim.x + threadIdx.x;
    if (i >= e) return;
    int d = edge_val(ei, (long long)e + i);
    atomicAdd(&g_cnt[d], 1);
}

// block-wise exclusive scan of g_cnt -> g_rowptr (per-block), block totals -> g_bsum
__global__ void k_scan1(int n) {
    __shared__ int s[1024];
    int t = threadIdx.x;
    int i = blockIdx.x * 1024 + t;
    int v = (i < n) ? g_cnt[i] : 0;
    s[t] = v;
    __syncthreads();
    #pragma unroll
    for (int off = 1; off < 1024; off <<= 1) {
        int x = (t >= off) ? s[t - off] : 0;
        __syncthreads();
        s[t] += x;
        __syncthreads();
    }
    if (i < n) g_rowptr[i] = s[t] - v;     // exclusive within block
    if (t == 1023) g_bsum[blockIdx.x] = s[1023];
}

__global__ void k_scan2(int nb) {
    if (threadIdx.x == 0) {
        int run = 0;
        for (int b = 0; b < nb; b++) { int t = g_bsum[b]; g_bsum[b] = run; run += t; }
    }
}

__global__ void k_scan3(int n) {
    int i = blockIdx.x * blockDim.x + threadIdx.x;
    if (i >= n) return;
    int r = g_rowptr[i] + g_bsum[i >> 10];
    g_rowptr[i] = r;
    g_fill[i]   = r;
    g_dinv[i]   = rsqrtf((float)g_cnt[i] + 1.0f);  // +1 for self-loop
}

__global__ void k_fill(const void* __restrict__ ei, int e) {
    int i = blockIdx.x * blockDim.x + threadIdx.x;
    if (i >= e) return;
    int s = edge_val(ei, i);
    int d = edge_val(ei, (long long)e + i);
    int pos = atomicAdd(&g_fill[d], 1);
    g_col[pos] = s;
    g_wgt[pos] = g_dinv[s] * g_dinv[d];
}

// ---------------- GEMM: C[n,128] = A[n,K] @ W[K,128] ----------------
// Block: 256 threads, tile = 32 rows x 128 cols. Each thread: 4 rows x 4 cols.
template <int K>
__global__ __launch_bounds__(256) void k_gemm(const float* __restrict__ A,
                                              const float* __restrict__ W,
                                              float* __restrict__ C, int n) {
    __shared__ float sA[32][33];   // padded
    __shared__ float sW[32][128];
    int tid  = threadIdx.x;
    int row0 = blockIdx.x * 32;
    int rg   = (tid >> 5) * 4;     // warp id * 4 : row offset in tile
    int c0   = (tid & 31) * 4;     // lane * 4    : col offset

    float acc[4][4] = {};

    for (int k0 = 0; k0 < K; k0 += 32) {
        // A tile: 32x32
        #pragma unroll
        for (int i = 0; i < 4; i++) {
            int idx = tid + i * 256;
            int r = idx >> 5, kk = idx & 31;
            int grow = row0 + r, gk = k0 + kk;
            sA[r][kk] = (grow < n && gk < K) ? A[(size_t)grow * K + gk] : 0.f;
        }
        // W tile: 32x128
        #pragma unroll
        for (int i = 0; i < 16; i++) {
            int idx = tid + i * 256;
            int kk = idx >> 7, c = idx & 127;
            int gk = k0 + kk;
            sW[kk][c] = (gk < K) ? W[gk * HD + c] : 0.f;
        }
        __syncthreads();
        #pragma unroll
        for (int kk = 0; kk < 32; kk++) {
            float4 bv = *(const float4*)&sW[kk][c0];
            #pragma unroll
            for (int j = 0; j < 4; j++) {
                float a = sA[rg + j][kk];       // warp-uniform broadcast
                acc[j][0] += a * bv.x;
                acc[j][1] += a * bv.y;
                acc[j][2] += a * bv.z;
                acc[j][3] += a * bv.w;
            }
        }
        __syncthreads();
    }
    #pragma unroll
    for (int j = 0; j < 4; j++) {
        int grow = row0 + rg + j;
        if (grow < n) {
            float4 v = make_float4(acc[j][0], acc[j][1], acc[j][2], acc[j][3]);
            *(float4*)&C[(size_t)grow * HD + c0] = v;
        }
    }
}

// ---------------- Aggregation: out_i = tanh( sum_e w_e*h[col_e] + dinv_i^2*h_i + b ) ----
// One warp per node; each lane owns 4 contiguous feature columns (float4).
__global__ __launch_bounds__(256) void k_agg(const float* __restrict__ h,
                                             const float* __restrict__ bias,
                                             float* __restrict__ out, int n) {
    int w    = (blockIdx.x * blockDim.x + threadIdx.x) >> 5;
    int lane = threadIdx.x & 31;
    if (w >= n) return;
    int start = g_rowptr[w];
    int cnt   = g_cnt[w];

    float4 acc = make_float4(0.f, 0.f, 0.f, 0.f);
    for (int e = 0; e < cnt; e++) {
        int idx  = start + e;
        int s    = g_col[idx];
        float we = g_wgt[idx];
        float4 hv = *(const float4*)&h[(size_t)s * HD + lane * 4];
        acc.x += we * hv.x;
        acc.y += we * hv.y;
        acc.z += we * hv.z;
        acc.w += we * hv.w;
    }
    float di = g_dinv[w];
    float d2 = di * di;
    float4 hs = *(const float4*)&h[(size_t)w * HD + lane * 4];
    float4 bv = *(const float4*)&bias[lane * 4];
    acc.x = tanhf(acc.x + d2 * hs.x + bv.x);
    acc.y = tanhf(acc.y + d2 * hs.y + bv.y);
    acc.z = tanhf(acc.z + d2 * hs.z + bv.z);
    acc.w = tanhf(acc.w + d2 * hs.w + bv.w);
    *(float4*)&out[(size_t)w * HD + lane * 4] = acc;
}

// ---------------- launch ----------------
extern "C" void kernel_launch(void* const* d_in, const int* in_sizes, int n_in,
                              void* d_out, int out_size) {
    const float* x  = (const float*)d_in[0];
    const void*  ei = d_in[1];
    const float* W0 = (const float*)d_in[2];
    const float* b0 = (const float*)d_in[3];
    const float* W1 = (const float*)d_in[4];
    const float* b1 = (const float*)d_in[5];
    const float* W2 = (const float*)d_in[6];
    const float* b2 = (const float*)d_in[7];
    const float* W3 = (const float*)d_in[8];
    const float* b3 = (const float*)d_in[9];
    float* out = (float*)d_out;

    int n  = in_sizes[0] / NF;   // 100000
    int e  = in_sizes[1] / 2;    // 1600000
    int nb = (n + 1023) / 1024;

    float *hbuf, *abuf;
    cudaGetSymbolAddress((void**)&hbuf, g_h);
    cudaGetSymbolAddress((void**)&abuf, g_a);

    // edge dtype probe + CSR build + normalization (once per call)
    k_probe<<<1, 256>>>((const int*)ei);
    k_zero_cnt<<<(n + 255) / 256, 256>>>(n);
    k_count<<<(e + 255) / 256, 256>>>(ei, e);
    k_scan1<<<nb, 1024>>>(n);
    k_scan2<<<1, 32>>>(nb);
    k_scan3<<<(n + 255) / 256, 256>>>(n);
    k_fill<<<(e + 255) / 256, 256>>>(ei, e);

    int gemm_blocks = (n + 31) / 32;
    int agg_blocks  = (n * 32 + 255) / 256;

    // layer 0
    k_gemm<NF><<<gemm_blocks, 256>>>(x, W0, hbuf, n);
    k_agg<<<agg_blocks, 256>>>(hbuf, b0, abuf, n);
    // layer 1
    k_gemm<HD><<<gemm_blocks, 256>>>(abuf, W1, hbuf, n);
    k_agg<<<agg_blocks, 256>>>(hbuf, b1, abuf, n);
    // layer 2
    k_gemm<HD><<<gemm_blocks, 256>>>(abuf, W2, hbuf, n);
    k_agg<<<agg_blocks, 256>>>(hbuf, b2, abuf, n);
    // layer 3
    k_gemm<HD><<<gemm_blocks, 256>>>(abuf, W3, hbuf, n);
    k_agg<<<agg_blocks, 256>>>(hbuf, b3, out, n);
}